// round 2
// baseline (speedup 1.0000x reference)
#include <cuda_runtime.h>
#include <stdint.h>

// Problem constants (shape-fixed per reference: m=n=8192, k=64)
#define COLS    8192
#define KDIM    64
#define NCHUNK  128            // COLS / KDIM
#define THREADS 256
#define XPAD    68             // padded chunk stride (floats): kills bank conflicts, keeps 16B align
#define SMEM_FLOATS (KDIM*KDIM + NCHUNK*XPAD)
#define SMEM_BYTES  (SMEM_FLOATS * 4)

// One f32x2 packed FMA: acc(pair) += (xi,xi) * hpair
#define FMA_PAIR(accref, xx, hp) \
    asm("fma.rn.f32x2 %0, %1, %2, %0;" : "+l"(accref) : "l"(xx), "l"(hp))

__global__ __launch_bounds__(THREADS, 2)
void bdq_kernel(const float* __restrict__ x, const float* __restrict__ hmat,
                float* __restrict__ out)
{
    extern __shared__ float smem[];
    float* h_s = smem;                    // 64*64 floats, row-major (pairs contiguous)
    float* x_s = smem + KDIM * KDIM;      // 128 chunks * XPAD floats
    __shared__ float red[THREADS / 32];
    __shared__ float s_scale;

    const int t = threadIdx.x;
    const long row = blockIdx.x;

    // ---- stage h (4096 floats) ----
    #pragma unroll
    for (int p = 0; p < 4; ++p) {
        const int idx = p * (THREADS * 4) + t * 4;
        *(float4*)(h_s + idx) = *(const float4*)(hmat + idx);
    }
    // ---- stage x row (8192 floats), chunk-padded layout ----
    const float* xrow = x + row * (long)COLS;
    #pragma unroll
    for (int p = 0; p < 8; ++p) {
        const int n = p * (THREADS * 4) + t * 4;
        const float4 v = *(const float4*)(xrow + n);
        *(float4*)(x_s + (n >> 6) * XPAD + (n & 63)) = v;
    }
    __syncthreads();

    // thread t -> group g = t/8 handles chunks {g, g+32, g+64, g+96},
    // lane-in-group l = t%8 handles output columns j0..j0+7
    const int g  = t >> 3;
    const int j0 = (t & 7) << 3;

    unsigned long long acc[4][4];   // [chunk][pair]  (f32x2 packed accumulators)
    #pragma unroll
    for (int s = 0; s < 4; ++s)
        #pragma unroll
        for (int p = 0; p < 4; ++p)
            acc[s][p] = 0ull;

    const float* xb0 = x_s + (g      ) * XPAD;
    const float* xb1 = x_s + (g + 32 ) * XPAD;
    const float* xb2 = x_s + (g + 64 ) * XPAD;
    const float* xb3 = x_s + (g + 96 ) * XPAD;

    #pragma unroll 4
    for (int i4 = 0; i4 < KDIM; i4 += 4) {
        const float4 xv0 = *(const float4*)(xb0 + i4);
        const float4 xv1 = *(const float4*)(xb1 + i4);
        const float4 xv2 = *(const float4*)(xb2 + i4);
        const float4 xv3 = *(const float4*)(xb3 + i4);
        #pragma unroll
        for (int di = 0; di < 4; ++di) {
            const float* hr = h_s + (i4 + di) * KDIM + j0;
            const ulonglong2 hA = *(const ulonglong2*)(hr);       // pairs (j0,j0+1),(j0+2,j0+3)
            const ulonglong2 hB = *(const ulonglong2*)(hr + 4);   // pairs (j0+4..j0+7)

            const float x0 = (di == 0) ? xv0.x : (di == 1) ? xv0.y : (di == 2) ? xv0.z : xv0.w;
            const float x1 = (di == 0) ? xv1.x : (di == 1) ? xv1.y : (di == 2) ? xv1.z : xv1.w;
            const float x2 = (di == 0) ? xv2.x : (di == 1) ? xv2.y : (di == 2) ? xv2.z : xv2.w;
            const float x3 = (di == 0) ? xv3.x : (di == 1) ? xv3.y : (di == 2) ? xv3.z : xv3.w;

            unsigned long long xx0, xx1, xx2, xx3;
            asm("mov.b64 %0, {%1, %1};" : "=l"(xx0) : "f"(x0));
            asm("mov.b64 %0, {%1, %1};" : "=l"(xx1) : "f"(x1));
            asm("mov.b64 %0, {%1, %1};" : "=l"(xx2) : "f"(x2));
            asm("mov.b64 %0, {%1, %1};" : "=l"(xx3) : "f"(x3));

            FMA_PAIR(acc[0][0], xx0, hA.x); FMA_PAIR(acc[0][1], xx0, hA.y);
            FMA_PAIR(acc[0][2], xx0, hB.x); FMA_PAIR(acc[0][3], xx0, hB.y);
            FMA_PAIR(acc[1][0], xx1, hA.x); FMA_PAIR(acc[1][1], xx1, hA.y);
            FMA_PAIR(acc[1][2], xx1, hB.x); FMA_PAIR(acc[1][3], xx1, hB.y);
            FMA_PAIR(acc[2][0], xx2, hA.x); FMA_PAIR(acc[2][1], xx2, hA.y);
            FMA_PAIR(acc[2][2], xx2, hB.x); FMA_PAIR(acc[2][3], xx2, hB.y);
            FMA_PAIR(acc[3][0], xx3, hA.x); FMA_PAIR(acc[3][1], xx3, hA.y);
            FMA_PAIR(acc[3][2], xx3, hB.x); FMA_PAIR(acc[3][3], xx3, hB.y);
        }
    }

    // ---- unpack accumulators, local absmax ----
    float rv[4][8];
    float m = 0.0f;
    #pragma unroll
    for (int s = 0; s < 4; ++s) {
        #pragma unroll
        for (int p = 0; p < 4; ++p) {
            float lo, hi;
            asm("mov.b64 {%0, %1}, %2;" : "=f"(lo), "=f"(hi) : "l"(acc[s][p]));
            rv[s][2 * p]     = lo;
            rv[s][2 * p + 1] = hi;
            m = fmaxf(m, fmaxf(fabsf(lo), fabsf(hi)));
        }
    }

    // ---- CTA absmax reduction ----
    #pragma unroll
    for (int o = 16; o > 0; o >>= 1)
        m = fmaxf(m, __shfl_xor_sync(0xffffffffu, m, o));
    if ((t & 31) == 0) red[t >> 5] = m;
    __syncthreads();
    if (t == 0) {
        float mm = red[0];
        #pragma unroll
        for (int w = 1; w < THREADS / 32; ++w) mm = fmaxf(mm, red[w]);
        float sc = __fdiv_rn(mm, 127.0f);          // IEEE, matches reference absmax/127
        s_scale = (sc == 0.0f) ? 1.0f : sc;
    }
    __syncthreads();
    const float sc = s_scale;

    // ---- quantize (IEEE div + round-half-even, matching jnp.round) ----
    // Output dtype is float32: store the clipped integer-valued floats directly.
    float* orow = out + row * (long)COLS;
    #pragma unroll
    for (int s = 0; s < 4; ++s) {
        float q[8];
        #pragma unroll
        for (int qi = 0; qi < 8; ++qi) {
            float qf = rintf(__fdiv_rn(rv[s][qi], sc));
            q[qi] = fminf(fmaxf(qf, -128.0f), 127.0f);
        }
        float* dst = orow + (g + 32 * s) * KDIM + j0;
        *(float4*)(dst)     = make_float4(q[0], q[1], q[2], q[3]);
        *(float4*)(dst + 4) = make_float4(q[4], q[5], q[6], q[7]);
    }
}

extern "C" void kernel_launch(void* const* d_in, const int* in_sizes, int n_in,
                              void* d_out, int out_size)
{
    // metadata order: x (m*n floats), h (64*64 floats). Be defensive about order.
    const float* x;
    const float* h;
    long x_elems;
    if (in_sizes[0] > in_sizes[1]) {
        x = (const float*)d_in[0]; h = (const float*)d_in[1]; x_elems = in_sizes[0];
    } else {
        x = (const float*)d_in[1]; h = (const float*)d_in[0]; x_elems = in_sizes[1];
    }
    const int rows = (int)(x_elems / COLS);

    cudaFuncSetAttribute(bdq_kernel, cudaFuncAttributeMaxDynamicSharedMemorySize, SMEM_BYTES);
    bdq_kernel<<<rows, THREADS, SMEM_BYTES>>>(x, h, (float*)d_out);
}

// round 3
// speedup vs baseline: 1.4541x; 1.4541x over previous
#include <cuda_runtime.h>
#include <stdint.h>

// m=n=8192, k=64 fixed. Output dtype: float32 (quantized integer values).
#define COLS    8192
#define KDIM    64
#define RPC     2               // rows per CTA
#define THREADS 256
#define XPAD    68              // padded chunk stride (floats)
#define NCR     (RPC * 128)     // chunk-rows staged per CTA
#define SMEM_FLOATS (KDIM*KDIM + NCR*XPAD)
#define SMEM_BYTES  (SMEM_FLOATS * 4)

#define FMA_PAIR(accref, xx, hp) \
    asm("fma.rn.f32x2 %0, %1, %2, %0;" : "+l"(accref) : "l"(xx), "l"(hp))

__global__ __launch_bounds__(THREADS, 2)
void bdq2_kernel(const float* __restrict__ x, const float* __restrict__ hmat,
                 float* __restrict__ out)
{
    extern __shared__ float smem[];
    float* h_s = smem;                    // 64*64 floats, row-major
    float* x_s = smem + KDIM * KDIM;      // NCR chunk-rows * XPAD floats
    __shared__ float red0[THREADS / 32], red1[THREADS / 32];
    __shared__ float s_scale0, s_scale1;

    const int  t    = threadIdx.x;
    const long row0 = (long)blockIdx.x * RPC;

    // ---- stage h (4096 floats) ----
    #pragma unroll
    for (int p = 0; p < 4; ++p) {
        const int idx = p * (THREADS * 4) + t * 4;
        *(float4*)(h_s + idx) = *(const float4*)(hmat + idx);
    }
    // ---- stage RPC rows of x (16384 floats), chunk-padded ----
    const float* xrow = x + row0 * (long)COLS;
    #pragma unroll
    for (int p = 0; p < 4 * RPC * 2; ++p) {
        const int n = p * (THREADS * 4) + t * 4;
        const float4 v = *(const float4*)(xrow + n);
        *(float4*)(x_s + (n >> 6) * XPAD + (n & 63)) = v;
    }
    __syncthreads();

    // thread t: g = t/8 in [0,32), l = t%8.
    // columns handled: {l*4..l*4+3} and {l*4+32..l*4+35}  (conflict-free h loads)
    // chunk-sets: s = r*4 + q  ->  chunk-row  r*128 + q*32 + g   (r in [0,RPC), q in [0,4))
    const int g   = t >> 3;
    const int l   = t & 7;
    const int jlo = l << 2;

    unsigned long long acc[8][4];         // [set][pair]
    #pragma unroll
    for (int s = 0; s < 8; ++s)
        #pragma unroll
        for (int p = 0; p < 4; ++p)
            acc[s][p] = 0ull;

    const float* xbase = x_s + g * XPAD;  // + (r*128+q*32)*XPAD as compile-time offsets

    #pragma unroll 2
    for (int i4 = 0; i4 < KDIM; i4 += 4) {
        float4 xv[8];
        #pragma unroll
        for (int s = 0; s < 8; ++s) {
            const int r = s >> 2, q = s & 3;
            xv[s] = *(const float4*)(xbase + (r * 128 + q * 32) * XPAD + i4);
        }
        #pragma unroll
        for (int di = 0; di < 4; ++di) {
            const float* hr = h_s + (i4 + di) * KDIM + jlo;
            const ulonglong2 hA = *(const ulonglong2*)(hr);        // cols jlo..jlo+3
            const ulonglong2 hB = *(const ulonglong2*)(hr + 32);   // cols jlo+32..jlo+35

            #pragma unroll
            for (int s = 0; s < 8; ++s) {
                const float xi = (di == 0) ? xv[s].x : (di == 1) ? xv[s].y
                               : (di == 2) ? xv[s].z : xv[s].w;
                unsigned long long xx;
                asm("mov.b64 %0, {%1, %1};" : "=l"(xx) : "f"(xi));
                FMA_PAIR(acc[s][0], xx, hA.x);
                FMA_PAIR(acc[s][1], xx, hA.y);
                FMA_PAIR(acc[s][2], xx, hB.x);
                FMA_PAIR(acc[s][3], xx, hB.y);
            }
        }
    }

    // ---- unpack, per-row absmax ----
    float rv[8][8];
    float m0 = 0.0f, m1 = 0.0f;
    #pragma unroll
    for (int s = 0; s < 8; ++s) {
        float mm = 0.0f;
        #pragma unroll
        for (int p = 0; p < 4; ++p) {
            float lo, hi;
            asm("mov.b64 {%0, %1}, %2;" : "=f"(lo), "=f"(hi) : "l"(acc[s][p]));
            rv[s][2 * p]     = lo;
            rv[s][2 * p + 1] = hi;
            mm = fmaxf(mm, fmaxf(fabsf(lo), fabsf(hi)));
        }
        if (s < 4) m0 = fmaxf(m0, mm); else m1 = fmaxf(m1, mm);
    }

    // ---- CTA absmax reduction (both rows) ----
    #pragma unroll
    for (int o = 16; o > 0; o >>= 1) {
        m0 = fmaxf(m0, __shfl_xor_sync(0xffffffffu, m0, o));
        m1 = fmaxf(m1, __shfl_xor_sync(0xffffffffu, m1, o));
    }
    if ((t & 31) == 0) { red0[t >> 5] = m0; red1[t >> 5] = m1; }
    __syncthreads();
    if (t == 0) {
        float a = red0[0], b = red1[0];
        #pragma unroll
        for (int w = 1; w < THREADS / 32; ++w) {
            a = fmaxf(a, red0[w]);
            b = fmaxf(b, red1[w]);
        }
        float sa = __fdiv_rn(a, 127.0f);
        float sb = __fdiv_rn(b, 127.0f);
        s_scale0 = (sa == 0.0f) ? 1.0f : sa;
        s_scale1 = (sb == 0.0f) ? 1.0f : sb;
    }
    __syncthreads();
    const float sc0 = s_scale0, sc1 = s_scale1;

    // ---- quantize (IEEE div + round-half-even) and store as float32 ----
    #pragma unroll
    for (int s = 0; s < 8; ++s) {
        const int r = s >> 2, q = s & 3;
        const float sc = (r == 0) ? sc0 : sc1;
        float qv[8];
        #pragma unroll
        for (int e = 0; e < 8; ++e) {
            float qf = rintf(__fdiv_rn(rv[s][e], sc));
            qv[e] = fminf(fmaxf(qf, -128.0f), 127.0f);
        }
        float* dst = out + (row0 + r) * (long)COLS + (q * 32 + g) * KDIM + jlo;
        *(float4*)(dst)      = make_float4(qv[0], qv[1], qv[2], qv[3]);
        *(float4*)(dst + 32) = make_float4(qv[4], qv[5], qv[6], qv[7]);
    }
}

extern "C" void kernel_launch(void* const* d_in, const int* in_sizes, int n_in,
                              void* d_out, int out_size)
{
    const float* x;
    const float* h;
    long x_elems;
    if (in_sizes[0] > in_sizes[1]) {
        x = (const float*)d_in[0]; h = (const float*)d_in[1]; x_elems = in_sizes[0];
    } else {
        x = (const float*)d_in[1]; h = (const float*)d_in[0]; x_elems = in_sizes[1];
    }
    const int rows = (int)(x_elems / COLS);

    cudaFuncSetAttribute(bdq2_kernel, cudaFuncAttributeMaxDynamicSharedMemorySize, SMEM_BYTES);
    bdq2_kernel<<<rows / RPC, THREADS, SMEM_BYTES>>>(x, h, (float*)d_out);
}

// round 4
// speedup vs baseline: 1.5265x; 1.0498x over previous
#include <cuda_runtime.h>
#include <stdint.h>

// m=n=8192, k=64 fixed. Output dtype: float32 (quantized integer values).
#define COLS    8192
#define KDIM    64
#define RPC     2               // rows per CTA
#define THREADS 256
#define XPAD    68              // padded chunk stride (floats)
#define SMEM_FLOATS (KDIM*KDIM + RPC*128*XPAD)
#define SMEM_BYTES  (SMEM_FLOATS * 4)

#define FMA_PAIR(accref, xx, hp) \
    asm("fma.rn.f32x2 %0, %1, %2, %0;" : "+l"(accref) : "l"(xx), "l"(hp))

#define CPA16(dst_u32, src_ptr) \
    asm volatile("cp.async.cg.shared.global [%0], [%1], 16;" :: "r"(dst_u32), "l"(src_ptr))

__device__ __forceinline__ uint32_t cvta_smem(const void* p) {
    return (uint32_t)__cvta_generic_to_shared(p);
}

// Compute 4 chunk-sets (chunks q*32+g, q=0..3) of one row; 16 packed f32x2 accs.
__device__ __forceinline__ void compute_row(const float* __restrict__ h_s,
                                            const float* __restrict__ xrow_s,
                                            int g, int jlo,
                                            unsigned long long acc[4][4])
{
    #pragma unroll
    for (int q = 0; q < 4; ++q)
        #pragma unroll
        for (int p = 0; p < 4; ++p)
            acc[q][p] = 0ull;

    const float* xb = xrow_s + g * XPAD;

    #pragma unroll 4
    for (int i4 = 0; i4 < KDIM; i4 += 4) {
        float4 xv[4];
        #pragma unroll
        for (int q = 0; q < 4; ++q)
            xv[q] = *(const float4*)(xb + (q * 32) * XPAD + i4);

        #pragma unroll
        for (int di = 0; di < 4; ++di) {
            const float* hr = h_s + (i4 + di) * KDIM + jlo;
            const ulonglong2 hA = *(const ulonglong2*)(hr);        // cols jlo..jlo+3
            const ulonglong2 hB = *(const ulonglong2*)(hr + 32);   // cols jlo+32..+35

            #pragma unroll
            for (int q = 0; q < 4; ++q) {
                const float xi = (di == 0) ? xv[q].x : (di == 1) ? xv[q].y
                               : (di == 2) ? xv[q].z : xv[q].w;
                unsigned long long xx;
                asm("mov.b64 %0, {%1, %1};" : "=l"(xx) : "f"(xi));
                FMA_PAIR(acc[q][0], xx, hA.x);
                FMA_PAIR(acc[q][1], xx, hA.y);
                FMA_PAIR(acc[q][2], xx, hB.x);
                FMA_PAIR(acc[q][3], xx, hB.y);
            }
        }
    }
}

__global__ __launch_bounds__(THREADS, 2)
void bdq3_kernel(const float* __restrict__ x, const float* __restrict__ hmat,
                 float* __restrict__ out)
{
    extern __shared__ float smem[];
    float* h_s = smem;                      // 64*64
    float* x_s = smem + KDIM * KDIM;        // 2 rows * 128 chunks * XPAD
    __shared__ float red[THREADS / 32];
    __shared__ float s_inv;

    const int  t    = threadIdx.x;
    const long row0 = (long)blockIdx.x * RPC;
    const float* xg = x + row0 * (long)COLS;

    // ---- group 0: h (16KB) + x row0 (32KB) ----
    #pragma unroll
    for (int p = 0; p < 4; ++p) {
        const int n = p * (THREADS * 4) + t * 4;
        CPA16(cvta_smem(h_s + n), hmat + n);
    }
    #pragma unroll
    for (int p = 0; p < 8; ++p) {
        const int n = p * (THREADS * 4) + t * 4;
        CPA16(cvta_smem(x_s + (n >> 6) * XPAD + (n & 63)), xg + n);
    }
    asm volatile("cp.async.commit_group;");
    // ---- group 1: x row1 (32KB) ----
    #pragma unroll
    for (int p = 0; p < 8; ++p) {
        const int n = p * (THREADS * 4) + t * 4;
        CPA16(cvta_smem(x_s + 128 * XPAD + (n >> 6) * XPAD + (n & 63)), xg + COLS + n);
    }
    asm volatile("cp.async.commit_group;");

    const int g   = t >> 3;         // chunk-group 0..31
    const int jlo = (t & 7) << 2;   // columns jlo..jlo+3 and +32..+35

    asm volatile("cp.async.wait_group 1;");
    __syncthreads();

    // ================= per-row: compute, reduce, quantize, store =================
    #pragma unroll 1
    for (int r = 0; r < RPC; ++r) {
        unsigned long long acc[4][4];
        compute_row(h_s, x_s + r * 128 * XPAD, g, jlo, acc);

        // unpack + local absmax
        float rv[4][8];
        float m = 0.0f;
        #pragma unroll
        for (int q = 0; q < 4; ++q) {
            #pragma unroll
            for (int p = 0; p < 4; ++p) {
                float lo, hi;
                asm("mov.b64 {%0, %1}, %2;" : "=f"(lo), "=f"(hi) : "l"(acc[q][p]));
                rv[q][2 * p]     = lo;
                rv[q][2 * p + 1] = hi;
                m = fmaxf(m, fmaxf(fabsf(lo), fabsf(hi)));
            }
        }
        // CTA absmax -> inv = 127/absmax (single IEEE divide)
        #pragma unroll
        for (int o = 16; o > 0; o >>= 1)
            m = fmaxf(m, __shfl_xor_sync(0xffffffffu, m, o));
        if ((t & 31) == 0) red[t >> 5] = m;
        __syncthreads();
        if (t == 0) {
            float a = red[0];
            #pragma unroll
            for (int w = 1; w < THREADS / 32; ++w) a = fmaxf(a, red[w]);
            s_inv = (a == 0.0f) ? 1.0f : __fdiv_rn(127.0f, a);
        }
        __syncthreads();
        const float inv = s_inv;

        // quantize + store (float32 output of integer values)
        float* orow = out + (row0 + r) * (long)COLS;
        #pragma unroll
        for (int q = 0; q < 4; ++q) {
            float qv[8];
            #pragma unroll
            for (int e = 0; e < 8; ++e) {
                float qf = rintf(rv[q][e] * inv);
                qv[e] = fminf(fmaxf(qf, -128.0f), 127.0f);
            }
            float* dst = orow + (q * 32 + g) * KDIM + jlo;
            *(float4*)(dst)      = make_float4(qv[0], qv[1], qv[2], qv[3]);
            *(float4*)(dst + 32) = make_float4(qv[4], qv[5], qv[6], qv[7]);
        }

        if (r == 0) {
            asm volatile("cp.async.wait_group 0;");
            __syncthreads();   // row1 data ready; also isolates red[] reuse
        }
    }
}

extern "C" void kernel_launch(void* const* d_in, const int* in_sizes, int n_in,
                              void* d_out, int out_size)
{
    const float* x;
    const float* h;
    long x_elems;
    if (in_sizes[0] > in_sizes[1]) {
        x = (const float*)d_in[0]; h = (const float*)d_in[1]; x_elems = in_sizes[0];
    } else {
        x = (const float*)d_in[1]; h = (const float*)d_in[0]; x_elems = in_sizes[1];
    }
    const int rows = (int)(x_elems / COLS);

    cudaFuncSetAttribute(bdq3_kernel, cudaFuncAttributeMaxDynamicSharedMemorySize, SMEM_BYTES);
    bdq3_kernel<<<rows / RPC, THREADS, SMEM_BYTES>>>(x, h, (float*)d_out);
}